// round 1
// baseline (speedup 1.0000x reference)
#include <cuda_runtime.h>
#include <math.h>

typedef long long ll;

#define SQ     2048   // sequence length
#define DIM    2048   // hidden dim
#define NHEADS 16
#define NKV    4
#define HDIM   128
#define KVD    512    // NKV*HDIM
#define NEXP   8
#define FDIM   2048
#define NTOK   2048

static const float kScaling = 0.08838834764831845f;  // 128^-0.5

// ----------------------------- scratch (device globals; no allocations) ----
__device__ float g_hsn   [(ll)NTOK*DIM];
__device__ float g_q     [(ll)NTOK*DIM];
__device__ float g_k     [(ll)NTOK*KVD];
__device__ float g_v     [(ll)NTOK*KVD];
__device__ float g_scores[(ll)NHEADS*SQ*SQ];   // 256 MB
__device__ float g_attn  [(ll)NTOK*DIM];
__device__ float g_hs2   [(ll)NTOK*DIM];
__device__ float g_t     [(ll)NTOK*DIM];
__device__ float g_tg    [(ll)NTOK*DIM];
__device__ float g_gu    [(ll)NTOK*2*FDIM];
__device__ float g_act   [(ll)NTOK*FDIM];
__device__ float g_routed[(ll)NTOK*DIM];
__device__ float g_sg    [(ll)NTOK*FDIM];
__device__ float g_su    [(ll)NTOK*FDIM];
__device__ float g_shared[(ll)NTOK*DIM];
__device__ int   g_eidx[NTOK];
__device__ float g_gateval[NTOK];
__device__ int   g_hist[NEXP], g_ctr[NEXP], g_seg_start[NEXP+1], g_seg_count[NEXP];
__device__ int   g_perm[NTOK];

// ----------------------------- generic 64x64x16 fp32 GEMM core ------------
// A[M,K] row-major (lda). If TB: B is [N,K] row-major (ldb), C = A*B^T.
// Else: B is [K,N] row-major (ldb). C[M,N] (ldc). Optional Cadd (same ldc, row m).
// Optional rowmap: C row index = rowmap[m] (scatter store for MoE).
// KCAP: limit K to m0+64 (causal PV). Requires N % 64 == 0, K % 16 == 0, lda/ldb/ldc % 4 == 0.
template<bool TB, bool KCAP>
__device__ __forceinline__ void gemm_body(
    const float* __restrict__ A, const float* __restrict__ B,
    float* __restrict__ C, const float* __restrict__ Cadd,
    int M, int K, int lda, int ldb, int ldc,
    int m0, int n0, const int* __restrict__ rowmap)
{
    __shared__ float As[16][68];
    __shared__ float Bs[16][68];
    const int tid = threadIdx.x;
    const int tr = tid >> 4;          // 0..15
    const int tc = tid & 15;          // 0..15
    const int ar = tid >> 2;          // 0..63
    const int ac = (tid & 3) << 2;    // 0,4,8,12
    float acc[4][4] = {};
    int Keff = K;
    if (KCAP) Keff = min(K, m0 + 64);

    for (int k0 = 0; k0 < Keff; k0 += 16) {
        // A tile -> As[k][m]
        {
            float4 va = make_float4(0.f, 0.f, 0.f, 0.f);
            int am = m0 + ar;
            if (am < M)
                va = *reinterpret_cast<const float4*>(A + (ll)am*lda + k0 + ac);
            As[ac+0][ar] = va.x; As[ac+1][ar] = va.y;
            As[ac+2][ar] = va.z; As[ac+3][ar] = va.w;
        }
        if (TB) {
            float4 vb = *reinterpret_cast<const float4*>(B + (ll)(n0 + ar)*ldb + k0 + ac);
            Bs[ac+0][ar] = vb.x; Bs[ac+1][ar] = vb.y;
            Bs[ac+2][ar] = vb.z; Bs[ac+3][ar] = vb.w;
        } else {
            int br = tid >> 4;
            int bc = (tid & 15) << 2;
            float4 vb = *reinterpret_cast<const float4*>(B + (ll)(k0 + br)*ldb + n0 + bc);
            *reinterpret_cast<float4*>(&Bs[br][bc]) = vb;
        }
        __syncthreads();
#pragma unroll
        for (int kk = 0; kk < 16; kk++) {
            float4 a4 = *reinterpret_cast<const float4*>(&As[kk][tr << 2]);
            float4 b4 = *reinterpret_cast<const float4*>(&Bs[kk][tc << 2]);
            acc[0][0] = fmaf(a4.x, b4.x, acc[0][0]);
            acc[0][1] = fmaf(a4.x, b4.y, acc[0][1]);
            acc[0][2] = fmaf(a4.x, b4.z, acc[0][2]);
            acc[0][3] = fmaf(a4.x, b4.w, acc[0][3]);
            acc[1][0] = fmaf(a4.y, b4.x, acc[1][0]);
            acc[1][1] = fmaf(a4.y, b4.y, acc[1][1]);
            acc[1][2] = fmaf(a4.y, b4.z, acc[1][2]);
            acc[1][3] = fmaf(a4.y, b4.w, acc[1][3]);
            acc[2][0] = fmaf(a4.z, b4.x, acc[2][0]);
            acc[2][1] = fmaf(a4.z, b4.y, acc[2][1]);
            acc[2][2] = fmaf(a4.z, b4.z, acc[2][2]);
            acc[2][3] = fmaf(a4.z, b4.w, acc[2][3]);
            acc[3][0] = fmaf(a4.w, b4.x, acc[3][0]);
            acc[3][1] = fmaf(a4.w, b4.y, acc[3][1]);
            acc[3][2] = fmaf(a4.w, b4.z, acc[3][2]);
            acc[3][3] = fmaf(a4.w, b4.w, acc[3][3]);
        }
        __syncthreads();
    }
#pragma unroll
    for (int i = 0; i < 4; i++) {
        int m = m0 + (tr << 2) + i;
        if (m < M) {
            int srow = rowmap ? rowmap[m] : m;
            float4 v = make_float4(acc[i][0], acc[i][1], acc[i][2], acc[i][3]);
            if (Cadd) {
                float4 a = *reinterpret_cast<const float4*>(Cadd + (ll)m*ldc + n0 + (tc << 2));
                v.x += a.x; v.y += a.y; v.z += a.z; v.w += a.w;
            }
            *reinterpret_cast<float4*>(C + (ll)srow*ldc + n0 + (tc << 2)) = v;
        }
    }
}

template<bool TB, bool CSKIP, bool KCAP>
__global__ void __launch_bounds__(256) gemm64(
    const float* __restrict__ A, const float* __restrict__ B,
    float* __restrict__ C, const float* __restrict__ Cadd,
    int M, int K, int lda, int ldb, int ldc,
    ll sA, ll sB, int zdivB, ll sC)
{
    int z  = blockIdx.z;
    int m0 = blockIdx.x << 6;
    int n0 = blockIdx.y << 6;
    if (CSKIP && n0 > m0 + 63) return;   // fully-masked causal tile
    gemm_body<TB, KCAP>(A + (ll)z*sA, B + (ll)(z / zdivB)*sB,
                        C + (ll)z*sC, Cadd ? (Cadd + (ll)z*sC) : nullptr,
                        M, K, lda, ldb, ldc, m0, n0, nullptr);
}

// ----------------------------- MoE grouped GEMMs --------------------------
__global__ void __launch_bounds__(256) gemm_expert_gateup(
    const float* __restrict__ tg, const float* __restrict__ gup, float* __restrict__ gu)
{
    int e = blockIdx.z;
    int cnt = g_seg_count[e];
    int m0 = blockIdx.x << 6;
    if (m0 >= cnt) return;
    int st = g_seg_start[e];
    gemm_body<false, false>(tg + (ll)st*DIM, gup + (ll)e*DIM*2*FDIM,
                            gu + (ll)st*2*FDIM, nullptr,
                            cnt, DIM, DIM, 2*FDIM, 2*FDIM,
                            m0, blockIdx.y << 6, nullptr);
}

__global__ void __launch_bounds__(256) gemm_expert_down(
    const float* __restrict__ act, const float* __restrict__ dwn, float* __restrict__ outr)
{
    int e = blockIdx.z;
    int cnt = g_seg_count[e];
    int m0 = blockIdx.x << 6;
    if (m0 >= cnt) return;
    int st = g_seg_start[e];
    gemm_body<false, false>(act + (ll)st*FDIM, dwn + (ll)e*FDIM*DIM,
                            outr, nullptr,
                            cnt, FDIM, FDIM, DIM, DIM,
                            m0, blockIdx.y << 6, g_perm + st);
}

// ----------------------------- elementwise / norm kernels ------------------
__global__ void __launch_bounds__(256) rmsnorm_kernel(
    const float* __restrict__ x, const float* __restrict__ w, float* __restrict__ y)
{
    int row = blockIdx.x, tid = threadIdx.x;
    const float* xr = x + (ll)row*DIM;
    float s = 0.f;
    for (int d = tid; d < DIM; d += 256) { float v = xr[d]; s = fmaf(v, v, s); }
    __shared__ float red[256];
    red[tid] = s; __syncthreads();
    for (int o = 128; o > 0; o >>= 1) { if (tid < o) red[tid] += red[tid+o]; __syncthreads(); }
    float inv = rsqrtf(red[0] * (1.0f/DIM) + 1e-5f);
    float* yr = y + (ll)row*DIM;
    for (int d = tid; d < DIM; d += 256) yr[d] = xr[d] * inv * w[d];
}

// RoPE (interleaved pairs) + L2 norm per (token, head)
__global__ void rope_l2_kernel(float* __restrict__ buf, const float* __restrict__ cosb,
                               const float* __restrict__ sinb, int ld)
{
    int s = blockIdx.x, h = blockIdx.y, j = threadIdx.x;  // j: 0..63
    float* p = buf + (ll)s*ld + h*HDIM;
    float a = p[2*j], b = p[2*j+1];
    float c  = cosb[s*64 + j];
    float sn = sinb[s*64 + j];
    float na = a*c - b*sn;
    float nb = a*sn + b*c;
    __shared__ float red[64];
    red[j] = na*na + nb*nb; __syncthreads();
    for (int o = 32; o > 0; o >>= 1) { if (j < o) red[j] += red[j+o]; __syncthreads(); }
    float scale = rsqrtf(red[0] * (1.0f/HDIM) + 1e-6f);
    p[2*j]   = na * scale;
    p[2*j+1] = nb * scale;
}

__global__ void __launch_bounds__(256) softmax_causal(float* __restrict__ scores)
{
    int row = blockIdx.x, h = blockIdx.y, tid = threadIdx.x;
    float* p = scores + ((ll)h*SQ + row)*SQ;
    int n = row + 1;
    __shared__ float red[256];
    float mx = -1e30f;
    for (int j = tid; j < n; j += 256) mx = fmaxf(mx, p[j]*kScaling);
    red[tid] = mx; __syncthreads();
    for (int o = 128; o > 0; o >>= 1) { if (tid < o) red[tid] = fmaxf(red[tid], red[tid+o]); __syncthreads(); }
    mx = red[0]; __syncthreads();
    float sum = 0.f;
    for (int j = tid; j < n; j += 256) {
        float e = expf(p[j]*kScaling - mx);
        p[j] = e; sum += e;
    }
    red[tid] = sum; __syncthreads();
    for (int o = 128; o > 0; o >>= 1) { if (tid < o) red[tid] += red[tid+o]; __syncthreads(); }
    float inv = 1.f / red[0];
    for (int j = tid; j < SQ; j += 256) p[j] = (j < n) ? p[j]*inv : 0.f;
}

__global__ void __launch_bounds__(256) router_kernel(
    const float* __restrict__ t, const float* __restrict__ rw)
{
    int row = blockIdx.x, tid = threadIdx.x;
    float acc[NEXP] = {};
    const float* xr = t + (ll)row*DIM;
    for (int d = tid; d < DIM; d += 256) {
        float x = xr[d];
        const float* r = rw + d*NEXP;
#pragma unroll
        for (int e = 0; e < NEXP; e++) acc[e] = fmaf(x, r[e], acc[e]);
    }
    __shared__ float red[NEXP][256];
#pragma unroll
    for (int e = 0; e < NEXP; e++) red[e][tid] = acc[e];
    __syncthreads();
    for (int o = 128; o > 0; o >>= 1) {
        if (tid < o)
#pragma unroll
            for (int e = 0; e < NEXP; e++) red[e][tid] += red[e][tid+o];
        __syncthreads();
    }
    if (tid == 0) {
        float best = red[0][0]; int bi = 0;
#pragma unroll
        for (int e = 1; e < NEXP; e++) if (red[e][0] > best) { best = red[e][0]; bi = e; }
        g_eidx[row] = bi;
        g_gateval[row] = 1.f / (1.f + expf(-best));
        atomicAdd(&g_hist[bi], 1);
    }
}

__global__ void zero8_kernel() {
    int i = threadIdx.x;
    if (i < NEXP) { g_hist[i] = 0; g_ctr[i] = 0; }
}

__global__ void prefix_kernel() {
    if (threadIdx.x == 0) {
        int s = 0;
        for (int e = 0; e < NEXP; e++) { g_seg_start[e] = s; g_seg_count[e] = g_hist[e]; s += g_hist[e]; }
        g_seg_start[NEXP] = s;
    }
}

__global__ void scatter_kernel() {
    int tk = blockIdx.x*256 + threadIdx.x;
    if (tk < NTOK) {
        int e = g_eidx[tk];
        int pos = atomicAdd(&g_ctr[e], 1);
        g_perm[g_seg_start[e] + pos] = tk;
    }
}

__global__ void __launch_bounds__(256) gather_scale_kernel(const float* __restrict__ t) {
    int i = blockIdx.x;
    int s = g_perm[i];
    float g = g_gateval[s];
    const float* src = t + (ll)s*DIM;
    float* dst = g_tg + (ll)i*DIM;
    for (int d = threadIdx.x; d < DIM; d += 256) dst[d] = src[d]*g;
}

__global__ void __launch_bounds__(256) act_routed_kernel(
    const float* __restrict__ gu, float* __restrict__ act)
{
    ll i = (ll)blockIdx.x*256 + threadIdx.x;       // over NTOK*FDIM
    ll row = i >> 11, f = i & (FDIM-1);
    float g = gu[row*2*FDIM + f];
    float u = gu[row*2*FDIM + FDIM + f];
    act[i] = u * (g / (1.f + expf(-g)));
}

__global__ void __launch_bounds__(256) swiglu_kernel(
    float* __restrict__ g, const float* __restrict__ u)
{
    ll i = (ll)blockIdx.x*256 + threadIdx.x;
    float x = g[i];
    g[i] = u[i] * (x / (1.f + expf(-x)));
}

__global__ void __launch_bounds__(256) final_add_kernel(
    const float* __restrict__ hs2, const float* __restrict__ shared_,
    const float* __restrict__ routed, float* __restrict__ out)
{
    ll i = (ll)blockIdx.x*256 + threadIdx.x;
    out[i] = hs2[i] + shared_[i] + routed[i];
}

// ----------------------------- launcher ------------------------------------
static float* symf(const void* sym) { void* p = nullptr; cudaGetSymbolAddress(&p, sym); return (float*)p; }

extern "C" void kernel_launch(void* const* d_in, const int* in_sizes, int n_in,
                              void* d_out, int out_size)
{
    (void)in_sizes; (void)n_in; (void)out_size;
    const float* hidden = (const float*)d_in[0];
    const float* fcos   = (const float*)d_in[1];
    const float* fsin   = (const float*)d_in[2];
    const float* wq     = (const float*)d_in[5];
    const float* wk     = (const float*)d_in[6];
    const float* wv     = (const float*)d_in[7];
    const float* wo     = (const float*)d_in[8];
    const float* ln1    = (const float*)d_in[9];
    const float* ln2    = (const float*)d_in[10];
    const float* rw     = (const float*)d_in[11];
    const float* gup    = (const float*)d_in[12];
    const float* dwn    = (const float*)d_in[13];
    const float* sgw    = (const float*)d_in[14];
    const float* suw    = (const float*)d_in[15];
    const float* sdw    = (const float*)d_in[16];
    float* out = (float*)d_out;

    float* hsn    = symf(g_hsn);
    float* qb     = symf(g_q);
    float* kb     = symf(g_k);
    float* vb     = symf(g_v);
    float* sc     = symf(g_scores);
    float* attn   = symf(g_attn);
    float* hs2    = symf(g_hs2);
    float* tb     = symf(g_t);
    float* tg     = symf(g_tg);
    float* gu     = symf(g_gu);
    float* actb   = symf(g_act);
    float* routed = symf(g_routed);
    float* sg     = symf(g_sg);
    float* su     = symf(g_su);
    float* shd    = symf(g_shared);

    // 1) pre-attn RMSNorm
    rmsnorm_kernel<<<NTOK, 256>>>(hidden, ln1, hsn);
    // 2) QKV projections
    gemm64<false,false,false><<<dim3(32,32,1),256>>>(hsn, wq, qb, nullptr, NTOK, DIM, DIM, DIM, DIM, 0,0,1,0);
    gemm64<false,false,false><<<dim3(32, 8,1),256>>>(hsn, wk, kb, nullptr, NTOK, DIM, DIM, KVD, KVD, 0,0,1,0);
    gemm64<false,false,false><<<dim3(32, 8,1),256>>>(hsn, wv, vb, nullptr, NTOK, DIM, DIM, KVD, KVD, 0,0,1,0);
    // 3) RoPE + L2 norm
    rope_l2_kernel<<<dim3(SQ, NHEADS), 64>>>(qb, fcos, fsin, DIM);
    rope_l2_kernel<<<dim3(SQ, NKV),    64>>>(kb, fcos, fsin, KVD);
    // 4) scores = Q K^T (per head, GQA via zdivB=4, causal tile skip)
    gemm64<true,true,false><<<dim3(32,32,NHEADS),256>>>(qb, kb, sc, nullptr,
        SQ, HDIM, DIM, KVD, SQ, /*sA*/HDIM, /*sB*/HDIM, /*zdivB*/NKV, /*sC*/(ll)SQ*SQ);
    // 5) causal softmax (scaling applied here)
    softmax_causal<<<dim3(SQ, NHEADS), 256>>>(sc);
    // 6) attn = P V (K capped causally)
    gemm64<false,false,true><<<dim3(32,2,NHEADS),256>>>(sc, vb, attn, nullptr,
        SQ, SQ, SQ, KVD, DIM, (ll)SQ*SQ, HDIM, NKV, HDIM);
    // 7) output proj + residual
    gemm64<false,false,false><<<dim3(32,32,1),256>>>(attn, wo, hs2, hidden, NTOK, DIM, DIM, DIM, DIM, 0,0,1,0);
    // 8) post-attn RMSNorm
    rmsnorm_kernel<<<NTOK, 256>>>(hs2, ln2, tb);
    // 9) router: top-1 expert + sigmoid gate; build permutation
    zero8_kernel<<<1, 32>>>();
    router_kernel<<<NTOK, 256>>>(tb, rw);
    prefix_kernel<<<1, 32>>>();
    scatter_kernel<<<8, 256>>>();
    gather_scale_kernel<<<NTOK, 256>>>(tb);
    // 10) routed expert: gate_up -> swiglu -> down (scatter back by perm)
    gemm_expert_gateup<<<dim3(32,64,NEXP),256>>>(tg, gup, gu);
    act_routed_kernel<<<(NTOK*FDIM)/256, 256>>>(gu, actb);
    gemm_expert_down<<<dim3(32,32,NEXP),256>>>(actb, dwn, routed);
    // 11) shared expert
    gemm64<false,false,false><<<dim3(32,32,1),256>>>(tb, sgw, sg, nullptr, NTOK, DIM, DIM, FDIM, FDIM, 0,0,1,0);
    gemm64<false,false,false><<<dim3(32,32,1),256>>>(tb, suw, su, nullptr, NTOK, DIM, DIM, FDIM, FDIM, 0,0,1,0);
    swiglu_kernel<<<(NTOK*FDIM)/256, 256>>>(sg, su);
    gemm64<false,false,false><<<dim3(32,32,1),256>>>(sg, sdw, shd, nullptr, NTOK, FDIM, FDIM, DIM, DIM, 0,0,1,0);
    // 12) final residual + shared + routed
    final_add_kernel<<<(NTOK*DIM)/256, 256>>>(hs2, shd, routed, out);
}

// round 4
// speedup vs baseline: 1.0545x; 1.0545x over previous
#include <cuda_runtime.h>
#include <cuda_bf16.h>
#include <cstdint>
#include <math.h>

typedef long long ll;

#define SQ     2048
#define DIM    2048
#define NHEADS 16
#define NKV    4
#define HDIM   128
#define KVD    512
#define NEXP   8
#define FDIM   2048
#define NTOK   2048

#define BM 128
#define BN 64
#define BK 16
#define LDK 20   // fp32 words per row; 20r mod 32 -> conflict-free fragment loads

static const float kScaling = 0.08838834764831845f;  // 128^-0.5

// ----------------------------- scratch (device globals) --------------------
__device__ float g_hsn   [(ll)NTOK*DIM];
__device__ float g_q     [(ll)NTOK*DIM];
__device__ float g_k     [(ll)NTOK*KVD];
__device__ float g_v     [(ll)NTOK*KVD];
__device__ float g_scores[(ll)NHEADS*SQ*SQ];   // 256 MB
__device__ float g_attn  [(ll)NTOK*DIM];
__device__ float g_hs2   [(ll)NTOK*DIM];
__device__ float g_t     [(ll)NTOK*DIM];
__device__ float g_tg    [(ll)NTOK*DIM];
__device__ float g_gu    [(ll)NTOK*2*FDIM];
__device__ float g_act   [(ll)NTOK*FDIM];
__device__ float g_routed[(ll)NTOK*DIM];
__device__ float g_sg    [(ll)NTOK*FDIM];
__device__ float g_su    [(ll)NTOK*FDIM];
__device__ float g_shared[(ll)NTOK*DIM];
__device__ int   g_eidx[NTOK];
__device__ float g_gateval[NTOK];
__device__ int   g_hist[NEXP], g_ctr[NEXP], g_seg_start[NEXP+1], g_seg_count[NEXP];
__device__ int   g_perm[NTOK];

// ----------------------------- helpers -------------------------------------
__device__ __forceinline__ uint32_t f2tf32(float x) {
    uint32_t r; asm("cvt.rna.tf32.f32 %0, %1;" : "=r"(r) : "f"(x)); return r;
}
__device__ __forceinline__ void tfsplit(float x, uint32_t& hi, uint32_t& lo) {
    hi = f2tf32(x);
    lo = f2tf32(x - __uint_as_float(hi));
}
__device__ __forceinline__ void mma_tf32(float* c, const uint32_t* a, const uint32_t* b) {
    asm volatile("mma.sync.aligned.m16n8k8.row.col.f32.tf32.tf32.f32 "
        "{%0,%1,%2,%3}, {%4,%5,%6,%7}, {%8,%9}, {%0,%1,%2,%3};"
        : "+f"(c[0]), "+f"(c[1]), "+f"(c[2]), "+f"(c[3])
        : "r"(a[0]), "r"(a[1]), "r"(a[2]), "r"(a[3]), "r"(b[0]), "r"(b[1]));
}

// ----------------------------- tensor GEMM body ----------------------------
// C[M,N] = A[M,K] * B, fp32 via 3xTF32 (per-register hi/lo split).
// BMODE=0: B is [N,K] row-major. BMODE=1: B is [K,N] row-major (transposed into smem).
// KCAP: limit K to m0+BM (causal PV). RM: scatter C rows through rowmap.
template<int BMODE, bool KCAP, bool RM>
__device__ __forceinline__ void hm_body(
    const float* __restrict__ A, const float* __restrict__ B,
    float* __restrict__ C, const float* __restrict__ Cadd,
    int M, int K, int lda, int ldb, int ldc, int m0, int n0,
    const int* __restrict__ rowmap)
{
    __shared__ float As[BM][LDK];   // 10240 B
    __shared__ float Bs[BN][LDK];   //  5120 B

    const int tid = threadIdx.x;
    const int wid = tid >> 5, lid = tid & 31;
    const int wm = (wid & 3) << 5;       // warp M offset: 0,32,64,96
    const int wn = (wid >> 2) << 5;      // warp N offset: 0,32
    const int lr = lid >> 2;             // groupID: 0..7
    const int ca = lid & 3;              // thread-in-group: 0..3
    const int lc = ca << 1;              // C fragment col base

    float acc[2][4][4];
#pragma unroll
    for (int i = 0; i < 2; i++)
#pragma unroll
        for (int j = 0; j < 4; j++)
#pragma unroll
            for (int q = 0; q < 4; q++) acc[i][j][q] = 0.f;

    int Keff = K;
    if (KCAP) Keff = min(K, m0 + BM);

    for (int k0 = 0; k0 < Keff; k0 += BK) {
        // ---- A tile: 128x16 fp32 ----
#pragma unroll
        for (int i = 0; i < 2; i++) {
            int idx = tid + (i << 8);          // 0..511
            int row = idx >> 2;
            int c4  = (idx & 3) << 2;
            float4 v = make_float4(0.f, 0.f, 0.f, 0.f);
            if ((m0 + row) < M)
                v = *reinterpret_cast<const float4*>(A + (ll)(m0 + row)*lda + k0 + c4);
            *reinterpret_cast<float4*>(&As[row][c4]) = v;
        }
        // ---- B tile: 64x16 fp32, [n][k] ----
        if (BMODE == 0) {
            int row = tid >> 2;
            int c4  = (tid & 3) << 2;
            float4 v = *reinterpret_cast<const float4*>(B + (ll)(n0 + row)*ldb + k0 + c4);
            *reinterpret_cast<float4*>(&Bs[row][c4]) = v;
        } else {
            int kr = tid >> 4;                 // 0..15
            int n4 = (tid & 15) << 2;          // 0..60
            float4 v = *reinterpret_cast<const float4*>(B + (ll)(k0 + kr)*ldb + n0 + n4);
            Bs[n4+0][kr] = v.x;
            Bs[n4+1][kr] = v.y;
            Bs[n4+2][kr] = v.z;
            Bs[n4+3][kr] = v.w;
        }
        __syncthreads();

#pragma unroll
        for (int ks = 0; ks < BK; ks += 8) {
            uint32_t ah[2][4], al[2][4];
#pragma unroll
            for (int mt = 0; mt < 2; mt++) {
                int r = wm + mt*16 + lr;
                tfsplit(As[r    ][ks + ca    ], ah[mt][0], al[mt][0]);
                tfsplit(As[r + 8][ks + ca    ], ah[mt][1], al[mt][1]);
                tfsplit(As[r    ][ks + ca + 4], ah[mt][2], al[mt][2]);
                tfsplit(As[r + 8][ks + ca + 4], ah[mt][3], al[mt][3]);
            }
            uint32_t bh[4][2], bl[4][2];
#pragma unroll
            for (int nt = 0; nt < 4; nt++) {
                int n = wn + nt*8 + lr;
                tfsplit(Bs[n][ks + ca    ], bh[nt][0], bl[nt][0]);
                tfsplit(Bs[n][ks + ca + 4], bh[nt][1], bl[nt][1]);
            }
#pragma unroll
            for (int mt = 0; mt < 2; mt++)
#pragma unroll
                for (int nt = 0; nt < 4; nt++) {
                    mma_tf32(acc[mt][nt], ah[mt], bh[nt]);
                    mma_tf32(acc[mt][nt], ah[mt], bl[nt]);
                    mma_tf32(acc[mt][nt], al[mt], bh[nt]);
                }
        }
        __syncthreads();
    }

    // ---- epilogue ----
#pragma unroll
    for (int mt = 0; mt < 2; mt++) {
        int mbase = m0 + wm + mt*16 + lr;
#pragma unroll
        for (int half = 0; half < 2; half++) {
            int m = mbase + half*8;
            if (m < M) {
                int srow = RM ? rowmap[m] : m;
#pragma unroll
                for (int nt = 0; nt < 4; nt++) {
                    int n = n0 + wn + nt*8 + lc;
                    float2 v = half ? make_float2(acc[mt][nt][2], acc[mt][nt][3])
                                    : make_float2(acc[mt][nt][0], acc[mt][nt][1]);
                    if (Cadd) {
                        float2 a = *reinterpret_cast<const float2*>(Cadd + (ll)m*ldc + n);
                        v.x += a.x; v.y += a.y;
                    }
                    *reinterpret_cast<float2*>(C + (ll)srow*ldc + n) = v;
                }
            }
        }
    }
}

// ----------------------------- GEMM wrappers -------------------------------
__global__ void __launch_bounds__(256) hm_dense(
    const float* __restrict__ A, const float* __restrict__ B,
    float* __restrict__ C, const float* __restrict__ Cadd,
    int M, int K, int lda, int ldb, int ldc)
{
    hm_body<1, false, false>(A, B, C, Cadd, M, K, lda, ldb, ldc,
                             blockIdx.x << 7, blockIdx.y << 6, nullptr);
}

__global__ void __launch_bounds__(256) hm_qk(
    const float* __restrict__ q, const float* __restrict__ k, float* __restrict__ scv)
{
    int h = blockIdx.z;
    int m0 = blockIdx.x << 7, n0 = blockIdx.y << 6;
    if (n0 > m0 + (BM - 1)) return;   // fully-masked causal tile
    hm_body<0, false, false>(q + h*HDIM, k + (h >> 2)*HDIM, scv + (ll)h*SQ*SQ, nullptr,
                             SQ, HDIM, DIM, KVD, SQ, m0, n0, nullptr);
}

__global__ void __launch_bounds__(256) hm_pv(
    const float* __restrict__ p, const float* __restrict__ v, float* __restrict__ attn)
{
    int h = blockIdx.z;
    hm_body<1, true, false>(p + (ll)h*SQ*SQ, v + (h >> 2)*HDIM, attn + h*HDIM, nullptr,
                            SQ, SQ, SQ, KVD, DIM, blockIdx.x << 7, blockIdx.y << 6, nullptr);
}

__global__ void __launch_bounds__(256) hm_gateup(
    const float* __restrict__ tg, const float* __restrict__ gup, float* __restrict__ gu)
{
    int e = blockIdx.z;
    int cnt = g_seg_count[e];
    int m0 = blockIdx.x << 7;
    if (m0 >= cnt) return;
    int st = g_seg_start[e];
    hm_body<1, false, false>(tg + (ll)st*DIM, gup + (ll)e*DIM*2*FDIM, gu + (ll)st*2*FDIM, nullptr,
                             cnt, DIM, DIM, 2*FDIM, 2*FDIM, m0, blockIdx.y << 6, nullptr);
}

__global__ void __launch_bounds__(256) hm_down(
    const float* __restrict__ act, const float* __restrict__ dwn, float* __restrict__ outr)
{
    int e = blockIdx.z;
    int cnt = g_seg_count[e];
    int m0 = blockIdx.x << 7;
    if (m0 >= cnt) return;
    int st = g_seg_start[e];
    hm_body<1, false, true>(act + (ll)st*FDIM, dwn + (ll)e*FDIM*DIM, outr, nullptr,
                            cnt, FDIM, FDIM, DIM, DIM, m0, blockIdx.y << 6, g_perm + st);
}

// ----------------------------- elementwise / norm kernels ------------------
__global__ void __launch_bounds__(256) rmsnorm_kernel(
    const float* __restrict__ x, const float* __restrict__ w, float* __restrict__ y)
{
    int row = blockIdx.x, tid = threadIdx.x;
    const float* xr = x + (ll)row*DIM;
    float s = 0.f;
    for (int d = tid; d < DIM; d += 256) { float v = xr[d]; s = fmaf(v, v, s); }
    __shared__ float red[256];
    red[tid] = s; __syncthreads();
    for (int o = 128; o > 0; o >>= 1) { if (tid < o) red[tid] += red[tid+o]; __syncthreads(); }
    float inv = rsqrtf(red[0] * (1.0f/DIM) + 1e-5f);
    float* yr = y + (ll)row*DIM;
    for (int d = tid; d < DIM; d += 256) yr[d] = xr[d] * inv * w[d];
}

__global__ void rope_l2_kernel(float* __restrict__ buf, const float* __restrict__ cosb,
                               const float* __restrict__ sinb, int ld)
{
    int s = blockIdx.x, h = blockIdx.y, j = threadIdx.x;  // j: 0..63
    float* p = buf + (ll)s*ld + h*HDIM;
    float a = p[2*j], b = p[2*j+1];
    float c  = cosb[s*64 + j];
    float sn = sinb[s*64 + j];
    float na = a*c - b*sn;
    float nb = a*sn + b*c;
    __shared__ float red[64];
    red[j] = na*na + nb*nb; __syncthreads();
    for (int o = 32; o > 0; o >>= 1) { if (j < o) red[j] += red[j+o]; __syncthreads(); }
    float scale = rsqrtf(red[0] * (1.0f/HDIM) + 1e-6f);
    p[2*j]   = na * scale;
    p[2*j+1] = nb * scale;
}

__global__ void __launch_bounds__(256) softmax_causal(float* __restrict__ scores)
{
    int row = blockIdx.x, h = blockIdx.y, tid = threadIdx.x;
    float* p = scores + ((ll)h*SQ + row)*SQ;
    int n = row + 1;
    __shared__ float red[256];
    float mx = -1e30f;
    for (int j = tid; j < n; j += 256) mx = fmaxf(mx, p[j]*kScaling);
    red[tid] = mx; __syncthreads();
    for (int o = 128; o > 0; o >>= 1) { if (tid < o) red[tid] = fmaxf(red[tid], red[tid+o]); __syncthreads(); }
    mx = red[0]; __syncthreads();
    float sum = 0.f;
    for (int j = tid; j < n; j += 256) {
        float e = expf(p[j]*kScaling - mx);
        p[j] = e; sum += e;
    }
    red[tid] = sum; __syncthreads();
    for (int o = 128; o > 0; o >>= 1) { if (tid < o) red[tid] += red[tid+o]; __syncthreads(); }
    float inv = 1.f / red[0];
    for (int j = tid; j < SQ; j += 256) p[j] = (j < n) ? p[j]*inv : 0.f;
}

__global__ void __launch_bounds__(256) router_kernel(
    const float* __restrict__ t, const float* __restrict__ rw)
{
    int row = blockIdx.x, tid = threadIdx.x;
    float acc[NEXP] = {};
    const float* xr = t + (ll)row*DIM;
    for (int d = tid; d < DIM; d += 256) {
        float x = xr[d];
        const float* r = rw + d*NEXP;
#pragma unroll
        for (int e = 0; e < NEXP; e++) acc[e] = fmaf(x, r[e], acc[e]);
    }
    __shared__ float red[NEXP][256];
#pragma unroll
    for (int e = 0; e < NEXP; e++) red[e][tid] = acc[e];
    __syncthreads();
    for (int o = 128; o > 0; o >>= 1) {
        if (tid < o)
#pragma unroll
            for (int e = 0; e < NEXP; e++) red[e][tid] += red[e][tid+o];
        __syncthreads();
    }
    if (tid == 0) {
        float best = red[0][0]; int bi = 0;
#pragma unroll
        for (int e = 1; e < NEXP; e++) if (red[e][0] > best) { best = red[e][0]; bi = e; }
        g_eidx[row] = bi;
        g_gateval[row] = 1.f / (1.f + expf(-best));
        atomicAdd(&g_hist[bi], 1);
    }
}

__global__ void zero8_kernel() {
    int i = threadIdx.x;
    if (i < NEXP) { g_hist[i] = 0; g_ctr[i] = 0; }
}

__global__ void prefix_kernel() {
    if (threadIdx.x == 0) {
        int s = 0;
        for (int e = 0; e < NEXP; e++) { g_seg_start[e] = s; g_seg_count[e] = g_hist[e]; s += g_hist[e]; }
        g_seg_start[NEXP] = s;
    }
}

__global__ void scatter_kernel() {
    int tk = blockIdx.x*256 + threadIdx.x;
    if (tk < NTOK) {
        int e = g_eidx[tk];
        int pos = atomicAdd(&g_ctr[e], 1);
        g_perm[g_seg_start[e] + pos] = tk;
    }
}

__global__ void __launch_bounds__(256) gather_scale_kernel(const float* __restrict__ t) {
    int i = blockIdx.x;
    int s = g_perm[i];
    float g = g_gateval[s];
    const float* src = t + (ll)s*DIM;
    float* dst = g_tg + (ll)i*DIM;
    for (int d = threadIdx.x; d < DIM; d += 256) dst[d] = src[d]*g;
}

__global__ void __launch_bounds__(256) act_routed_kernel(
    const float* __restrict__ gu, float* __restrict__ act)
{
    ll i = (ll)blockIdx.x*256 + threadIdx.x;
    ll row = i >> 11, f = i & (FDIM-1);
    float g = gu[row*2*FDIM + f];
    float u = gu[row*2*FDIM + FDIM + f];
    act[i] = u * (g / (1.f + expf(-g)));
}

__global__ void __launch_bounds__(256) swiglu_kernel(
    float* __restrict__ g, const float* __restrict__ u)
{
    ll i = (ll)blockIdx.x*256 + threadIdx.x;
    float x = g[i];
    g[i] = u[i] * (x / (1.f + expf(-x)));
}

__global__ void __launch_bounds__(256) final_add_kernel(
    const float* __restrict__ hs2, const float* __restrict__ shared_,
    const float* __restrict__ routed, float* __restrict__ out)
{
    ll i = (ll)blockIdx.x*256 + threadIdx.x;
    out[i] = hs2[i] + shared_[i] + routed[i];
}

// ----------------------------- launcher ------------------------------------
static float* symf(const void* sym) { void* p = nullptr; cudaGetSymbolAddress(&p, sym); return (float*)p; }

extern "C" void kernel_launch(void* const* d_in, const int* in_sizes, int n_in,
                              void* d_out, int out_size)
{
    (void)in_sizes; (void)n_in; (void)out_size;
    const float* hidden = (const float*)d_in[0];
    const float* fcos   = (const float*)d_in[1];
    const float* fsin   = (const float*)d_in[2];
    const float* wq     = (const float*)d_in[5];
    const float* wk     = (const float*)d_in[6];
    const float* wv     = (const float*)d_in[7];
    const float* wo     = (const float*)d_in[8];
    const float* ln1    = (const float*)d_in[9];
    const float* ln2    = (const float*)d_in[10];
    const float* rw     = (const float*)d_in[11];
    const float* gup    = (const float*)d_in[12];
    const float* dwn    = (const float*)d_in[13];
    const float* sgw    = (const float*)d_in[14];
    const float* suw    = (const float*)d_in[15];
    const float* sdw    = (const float*)d_in[16];
    float* out = (float*)d_out;

    float* hsn    = symf(g_hsn);
    float* qb     = symf(g_q);
    float* kb     = symf(g_k);
    float* vb     = symf(g_v);
    float* sc     = symf(g_scores);
    float* attn   = symf(g_attn);
    float* hs2    = symf(g_hs2);
    float* tb     = symf(g_t);
    float* tg     = symf(g_tg);
    float* gu     = symf(g_gu);
    float* actb   = symf(g_act);
    float* routed = symf(g_routed);
    float* sg     = symf(g_sg);
    float* su     = symf(g_su);
    float* shd    = symf(g_shared);

    // 1) pre-attn RMSNorm
    rmsnorm_kernel<<<NTOK, 256>>>(hidden, ln1, hsn);
    // 2) QKV projections
    hm_dense<<<dim3(16,32), 256>>>(hsn, wq, qb, nullptr, NTOK, DIM, DIM, DIM, DIM);
    hm_dense<<<dim3(16, 8), 256>>>(hsn, wk, kb, nullptr, NTOK, DIM, DIM, KVD, KVD);
    hm_dense<<<dim3(16, 8), 256>>>(hsn, wv, vb, nullptr, NTOK, DIM, DIM, KVD, KVD);
    // 3) RoPE + L2 norm
    rope_l2_kernel<<<dim3(SQ, NHEADS), 64>>>(qb, fcos, fsin, DIM);
    rope_l2_kernel<<<dim3(SQ, NKV),    64>>>(kb, fcos, fsin, KVD);
    // 4) scores = Q K^T (causal tile skip)
    hm_qk<<<dim3(16,32,NHEADS), 256>>>(qb, kb, sc);
    // 5) causal softmax
    softmax_causal<<<dim3(SQ, NHEADS), 256>>>(sc);
    // 6) attn = P V (K capped causally)
    hm_pv<<<dim3(16,2,NHEADS), 256>>>(sc, vb, attn);
    // 7) output proj + residual
    hm_dense<<<dim3(16,32), 256>>>(attn, wo, hs2, hidden, NTOK, DIM, DIM, DIM, DIM);
    // 8) post-attn RMSNorm
    rmsnorm_kernel<<<NTOK, 256>>>(hs2, ln2, tb);
    // 9) router
    zero8_kernel<<<1, 32>>>();
    router_kernel<<<NTOK, 256>>>(tb, rw);
    prefix_kernel<<<1, 32>>>();
    scatter_kernel<<<8, 256>>>();
    gather_scale_kernel<<<NTOK, 256>>>(tb);
    // 10) routed expert
    hm_gateup<<<dim3(16,64,NEXP), 256>>>(tg, gup, gu);
    act_routed_kernel<<<(NTOK*FDIM)/256, 256>>>(gu, actb);
    hm_down<<<dim3(16,32,NEXP), 256>>>(actb, dwn, routed);
    // 11) shared expert
    hm_dense<<<dim3(16,32), 256>>>(tb, sgw, sg, nullptr, NTOK, DIM, DIM, FDIM, FDIM);
    hm_dense<<<dim3(16,32), 256>>>(tb, suw, su, nullptr, NTOK, DIM, DIM, FDIM, FDIM);
    swiglu_kernel<<<(NTOK*FDIM)/256, 256>>>(sg, su);
    hm_dense<<<dim3(16,32), 256>>>(sg, sdw, shd, nullptr, NTOK, FDIM, FDIM, DIM, DIM);
    // 12) final residual + shared + routed
    final_add_kernel<<<(NTOK*DIM)/256, 256>>>(hs2, shd, routed, out);
}

// round 6
// speedup vs baseline: 1.1561x; 1.0963x over previous
#include <cuda_runtime.h>
#include <cuda_bf16.h>
#include <cstdint>
#include <math.h>

typedef long long ll;

#define SQ     2048
#define DIM    2048
#define NHEADS 16
#define NKV    4
#define HDIM   128
#define KVD    512
#define NEXP   8
#define FDIM   2048
#define NTOK   2048

#define BM 128
#define BN 64
#define BK 32
#define LDA2 36   // A row stride in uint2 (32+4 pad)
#define LDB2 68   // B row stride in uint2 (64+4 pad)
#define SMEM_A_BYTES (BM*LDA2*8)            // 36864
#define SMEM_B_BYTES (BK*LDB2*8)            // 17408
#define SMEM_BYTES   (SMEM_A_BYTES + SMEM_B_BYTES)   // 54272

static const float kScaling = 0.08838834764831845f;  // 128^-0.5

// ----------------------------- scratch (device globals) --------------------
__device__ float g_hsn   [(ll)NTOK*DIM];
__device__ float g_q     [(ll)NTOK*DIM];
__device__ float g_k     [(ll)NTOK*KVD];
__device__ float g_v     [(ll)NTOK*KVD];
__device__ float g_scores[(ll)NHEADS*SQ*SQ];   // 256 MB
__device__ float g_attn  [(ll)NTOK*DIM];
__device__ float g_hs2   [(ll)NTOK*DIM];
__device__ float g_t     [(ll)NTOK*DIM];
__device__ float g_tg    [(ll)NTOK*DIM];
__device__ float g_gu    [(ll)NTOK*2*FDIM];
__device__ float g_act   [(ll)NTOK*FDIM];
__device__ float g_routed[(ll)NTOK*DIM];
__device__ float g_sg    [(ll)NTOK*FDIM];
__device__ float g_su    [(ll)NTOK*FDIM];
__device__ float g_shared[(ll)NTOK*DIM];
__device__ int   g_eidx[NTOK];
__device__ float g_gateval[NTOK];
__device__ int   g_hist[NEXP], g_ctr[NEXP], g_seg_start[NEXP+1], g_seg_count[NEXP];
__device__ int   g_perm[NTOK];

// ----------------------------- helpers -------------------------------------
__device__ __forceinline__ uint32_t f2tf32(float x) {
    uint32_t r; asm("cvt.rna.tf32.f32 %0, %1;" : "=r"(r) : "f"(x)); return r;
}
__device__ __forceinline__ uint2 tfsplit2(float x) {
    uint32_t hi = f2tf32(x);
    uint32_t lo = f2tf32(x - __uint_as_float(hi));
    return make_uint2(hi, lo);
}
__device__ __forceinline__ void mma_tf32(float* c, const uint32_t* a, const uint32_t* b) {
    asm volatile("mma.sync.aligned.m16n8k8.row.col.f32.tf32.tf32.f32 "
        "{%0,%1,%2,%3}, {%4,%5,%6,%7}, {%8,%9}, {%0,%1,%2,%3};"
        : "+f"(c[0]), "+f"(c[1]), "+f"(c[2]), "+f"(c[3])
        : "r"(a[0]), "r"(a[1]), "r"(a[2]), "r"(a[3]), "r"(b[0]), "r"(b[1]));
}

// ----------------------------- tensor GEMM body ----------------------------
// C[M,N] = A[M,K] * B, fp32 via 3xTF32; hi/lo pre-split into SMEM as uint2.
// SMEM: As[m][k] (uint2, LDA2 stride), Bs[k][n] (uint2, LDB2 stride).
// BMODE=0: B is [N,K] row-major (transposed on fill). BMODE=1: B is [K,N] row-major (natural fill).
// KCAP: limit K to m0+BM (causal PV). RM: scatter C rows through rowmap.
template<int BMODE, bool KCAP, bool RM>
__device__ __forceinline__ void hm_body(
    const float* __restrict__ A, const float* __restrict__ B,
    float* __restrict__ C, const float* __restrict__ Cadd,
    int M, int K, int lda, int ldb, int ldc, int m0, int n0,
    const int* __restrict__ rowmap)
{
    extern __shared__ char smem[];
    uint2* As = reinterpret_cast<uint2*>(smem);
    uint2* Bs = reinterpret_cast<uint2*>(smem + SMEM_A_BYTES);

    const int tid = threadIdx.x;
    const int wid = tid >> 5, lid = tid & 31;
    const int wm = (wid & 3) << 5;       // warp M offset: 0,32,64,96
    const int wn = (wid >> 2) << 5;      // warp N offset: 0,32
    const int lr = lid >> 2;             // groupID: 0..7
    const int ca = lid & 3;              // thread-in-group: 0..3
    const int lc = ca << 1;

    float acc[2][4][4];
#pragma unroll
    for (int i = 0; i < 2; i++)
#pragma unroll
        for (int j = 0; j < 4; j++)
#pragma unroll
            for (int q = 0; q < 4; q++) acc[i][j][q] = 0.f;

    int Keff = K;
    if (KCAP) Keff = min(K, m0 + BM);
    const int nch = Keff >> 5;   // BK=32 chunks

    float4 va[4], vb[2];

    // ---- prologue: load chunk 0 into regs ----
    {
        const int k0 = 0;
#pragma unroll
        for (int i = 0; i < 4; i++) {
            int idx = tid + (i << 8);
            int row = idx >> 3, c4 = (idx & 7) << 2;
            va[i] = make_float4(0.f, 0.f, 0.f, 0.f);
            if ((m0 + row) < M)
                va[i] = *reinterpret_cast<const float4*>(A + (ll)(m0 + row)*lda + k0 + c4);
        }
#pragma unroll
        for (int i = 0; i < 2; i++) {
            int idx = tid + (i << 8);
            if (BMODE == 1) {
                int kr = idx >> 4, n4 = (idx & 15) << 2;
                vb[i] = *reinterpret_cast<const float4*>(B + (ll)(k0 + kr)*ldb + n0 + n4);
            } else {
                int n = idx & 63, kc4 = (idx >> 6) << 2;
                vb[i] = *reinterpret_cast<const float4*>(B + (ll)(n0 + n)*ldb + k0 + kc4);
            }
        }
    }

    for (int c = 0; c < nch; c++) {
        // ---- store current chunk regs -> smem (split hi/lo once) ----
#pragma unroll
        for (int i = 0; i < 4; i++) {
            int idx = tid + (i << 8);
            int row = idx >> 3, c4 = (idx & 7) << 2;
            uint2* dst = &As[row*LDA2 + c4];
            dst[0] = tfsplit2(va[i].x);
            dst[1] = tfsplit2(va[i].y);
            dst[2] = tfsplit2(va[i].z);
            dst[3] = tfsplit2(va[i].w);
        }
#pragma unroll
        for (int i = 0; i < 2; i++) {
            int idx = tid + (i << 8);
            if (BMODE == 1) {
                int kr = idx >> 4, n4 = (idx & 15) << 2;
                uint2* dst = &Bs[kr*LDB2 + n4];
                dst[0] = tfsplit2(vb[i].x);
                dst[1] = tfsplit2(vb[i].y);
                dst[2] = tfsplit2(vb[i].z);
                dst[3] = tfsplit2(vb[i].w);
            } else {
                int n = idx & 63, kc4 = (idx >> 6) << 2;
                Bs[(kc4+0)*LDB2 + n] = tfsplit2(vb[i].x);
                Bs[(kc4+1)*LDB2 + n] = tfsplit2(vb[i].y);
                Bs[(kc4+2)*LDB2 + n] = tfsplit2(vb[i].z);
                Bs[(kc4+3)*LDB2 + n] = tfsplit2(vb[i].w);
            }
        }
        __syncthreads();

        // ---- prefetch next chunk into regs (overlaps with MMA below) ----
        if (c + 1 < nch) {
            const int k0 = (c + 1) << 5;
#pragma unroll
            for (int i = 0; i < 4; i++) {
                int idx = tid + (i << 8);
                int row = idx >> 3, c4 = (idx & 7) << 2;
                va[i] = make_float4(0.f, 0.f, 0.f, 0.f);
                if ((m0 + row) < M)
                    va[i] = *reinterpret_cast<const float4*>(A + (ll)(m0 + row)*lda + k0 + c4);
            }
#pragma unroll
            for (int i = 0; i < 2; i++) {
                int idx = tid + (i << 8);
                if (BMODE == 1) {
                    int kr = idx >> 4, n4 = (idx & 15) << 2;
                    vb[i] = *reinterpret_cast<const float4*>(B + (ll)(k0 + kr)*ldb + n0 + n4);
                } else {
                    int n = idx & 63, kc4 = (idx >> 6) << 2;
                    vb[i] = *reinterpret_cast<const float4*>(B + (ll)(n0 + n)*ldb + k0 + kc4);
                }
            }
        }

        // ---- compute: 4 k8-steps, all operands pre-split in smem ----
#pragma unroll
        for (int ks = 0; ks < BK; ks += 8) {
            uint2 bfr[4][2];
#pragma unroll
            for (int nt = 0; nt < 4; nt++) {
                int n = wn + nt*8 + lr;
                bfr[nt][0] = Bs[(ks + ca    )*LDB2 + n];
                bfr[nt][1] = Bs[(ks + ca + 4)*LDB2 + n];
            }
#pragma unroll
            for (int mt = 0; mt < 2; mt++) {
                int r = wm + mt*16 + lr;
                uint2 a0 = As[ r     *LDA2 + ks + ca    ];
                uint2 a1 = As[(r + 8)*LDA2 + ks + ca    ];
                uint2 a2 = As[ r     *LDA2 + ks + ca + 4];
                uint2 a3 = As[(r + 8)*LDA2 + ks + ca + 4];
                uint32_t ah[4] = {a0.x, a1.x, a2.x, a3.x};
                uint32_t al[4] = {a0.y, a1.y, a2.y, a3.y};
#pragma unroll
                for (int nt = 0; nt < 4; nt++) {
                    uint32_t bh[2] = {bfr[nt][0].x, bfr[nt][1].x};
                    uint32_t bl[2] = {bfr[nt][0].y, bfr[nt][1].y};
                    mma_tf32(acc[mt][nt], ah, bh);
                    mma_tf32(acc[mt][nt], ah, bl);
                    mma_tf32(acc[mt][nt], al, bh);
                }
            }
        }
        __syncthreads();
    }

    // ---- epilogue ----
#pragma unroll
    for (int mt = 0; mt < 2; mt++) {
        int mbase = m0 + wm + mt*16 + lr;
#pragma unroll
        for (int half = 0; half < 2; half++) {
            int m = mbase + half*8;
            if (m < M) {
                int srow = RM ? rowmap[m] : m;
#pragma unroll
                for (int nt = 0; nt < 4; nt++) {
                    int n = n0 + wn + nt*8 + lc;
                    float2 v = half ? make_float2(acc[mt][nt][2], acc[mt][nt][3])
                                    : make_float2(acc[mt][nt][0], acc[mt][nt][1]);
                    if (Cadd) {
                        float2 a = *reinterpret_cast<const float2*>(Cadd + (ll)m*ldc + n);
                        v.x += a.x; v.y += a.y;
                    }
                    *reinterpret_cast<float2*>(C + (ll)srow*ldc + n) = v;
                }
            }
        }
    }
}

// ----------------------------- GEMM wrappers -------------------------------
__global__ void __launch_bounds__(256, 2) hm_dense(
    const float* __restrict__ A, const float* __restrict__ B,
    float* __restrict__ C, const float* __restrict__ Cadd,
    int M, int K, int lda, int ldb, int ldc)
{
    hm_body<1, false, false>(A, B, C, Cadd, M, K, lda, ldb, ldc,
                             blockIdx.x << 7, blockIdx.y << 6, nullptr);
}

// z-batched pair of dense GEMMs (same A/shape, different B,C)
__global__ void __launch_bounds__(256, 2) hm_dense2(
    const float* __restrict__ A,
    const float* __restrict__ B0, float* __restrict__ C0,
    const float* __restrict__ B1, float* __restrict__ C1,
    int M, int K, int lda, int ldb, int ldc)
{
    const float* B = blockIdx.z ? B1 : B0;
    float* C = blockIdx.z ? C1 : C0;
    hm_body<1, false, false>(A, B, C, nullptr, M, K, lda, ldb, ldc,
                             blockIdx.x << 7, blockIdx.y << 6, nullptr);
}

__global__ void __launch_bounds__(256, 2) hm_qk(
    const float* __restrict__ q, const float* __restrict__ k, float* __restrict__ scv)
{
    int h = blockIdx.z;
    int m0 = blockIdx.x << 7, n0 = blockIdx.y << 6;
    if (n0 > m0 + (BM - 1)) return;   // fully-masked causal tile
    hm_body<0, false, false>(q + h*HDIM, k + (h >> 2)*HDIM, scv + (ll)h*SQ*SQ, nullptr,
                             SQ, HDIM, DIM, KVD, SQ, m0, n0, nullptr);
}

__global__ void __launch_bounds__(256, 2) hm_pv(
    const float* __restrict__ p, const float* __restrict__ v, float* __restrict__ attn)
{
    int h = blockIdx.z;
    hm_body<1, true, false>(p + (ll)h*SQ*SQ, v + (h >> 2)*HDIM, attn + h*HDIM, nullptr,
                            SQ, SQ, SQ, KVD, DIM, blockIdx.x << 7, blockIdx.y << 6, nullptr);
}

__global__ void __launch_bounds__(256, 2) hm_gateup(
    const float* __restrict__ tg, const float* __restrict__ gup, float* __restrict__ gu)
{
    int e = blockIdx.z;
    int cnt = g_seg_count[e];
    int m0 = blockIdx.x << 7;
    if (m0 >= cnt) return;
    int st = g_seg_start[e];
    hm_body<1, false, false>(tg + (ll)st*DIM, gup + (ll)e*DIM*2*FDIM, gu + (ll)st*2*FDIM, nullptr,
                             cnt, DIM, DIM, 2*FDIM, 2*FDIM, m0, blockIdx.y << 6, nullptr);
}

__global__ void __launch_bounds__(256, 2) hm_down(
    const float* __restrict__ act, const float* __restrict__ dwn, float* __restrict__ outr)
{
    int e = blockIdx.z;
    int cnt = g_seg_count[e];
    int m0 = blockIdx.x << 7;
    if (m0 >= cnt) return;
    int st = g_seg_start[e];
    hm_body<1, false, true>(act + (ll)st*FDIM, dwn + (ll)e*FDIM*DIM, outr, nullptr,
                            cnt, FDIM, FDIM, DIM, DIM, m0, blockIdx.y << 6, g_perm + st);
}

// ----------------------------- elementwise / norm kernels ------------------
__global__ void __launch_bounds__(256) rmsnorm_kernel(
    const float* __restrict__ x, const float* __restrict__ w, float* __restrict__ y)
{
    int row = blockIdx.x, tid = threadIdx.x;
    const float* xr = x + (ll)row*DIM;
    float s = 0.f;
    for (int d = tid; d < DIM; d += 256) { float v = xr[d]; s = fmaf(v, v, s); }
    __shared__ float red[256];
    red[tid] = s; __syncthreads();
    for (int o = 128; o > 0; o >>= 1) { if (tid < o) red[tid] += red[tid+o]; __syncthreads(); }
    float inv = rsqrtf(red[0] * (1.0f/DIM) + 1e-5f);
    float* yr = y + (ll)row*DIM;
    for (int d = tid; d < DIM; d += 256) yr[d] = xr[d] * inv * w[d];
}

__global__ void rope_l2_kernel(float* __restrict__ buf, const float* __restrict__ cosb,
                               const float* __restrict__ sinb, int ld)
{
    int s = blockIdx.x, h = blockIdx.y, j = threadIdx.x;  // j: 0..63
    float* p = buf + (ll)s*ld + h*HDIM;
    float a = p[2*j], b = p[2*j+1];
    float c  = cosb[s*64 + j];
    float sn = sinb[s*64 + j];
    float na = a*c - b*sn;
    float nb = a*sn + b*c;
    __shared__ float red[64];
    red[j] = na*na + nb*nb; __syncthreads();
    for (int o = 32; o > 0; o >>= 1) { if (j < o) red[j] += red[j+o]; __syncthreads(); }
    float scale = rsqrtf(red[0] * (1.0f/HDIM) + 1e-6f);
    p[2*j]   = na * scale;
    p[2*j+1] = nb * scale;
}

__global__ void __launch_bounds__(256) softmax_causal(float* __restrict__ scores)
{
    int row = blockIdx.x, h = blockIdx.y, tid = threadIdx.x;
    float* p = scores + ((ll)h*SQ + row)*SQ;
    int n = row + 1;
    int zend = ((row >> 7) << 7) + 128;   // PV only reads k < m0+128
    __shared__ float red[256];
    float mx = -1e30f;
    for (int j = tid; j < n; j += 256) mx = fmaxf(mx, p[j]*kScaling);
    red[tid] = mx; __syncthreads();
    for (int o = 128; o > 0; o >>= 1) { if (tid < o) red[tid] = fmaxf(red[tid], red[tid+o]); __syncthreads(); }
    mx = red[0]; __syncthreads();
    float sum = 0.f;
    for (int j = tid; j < n; j += 256) {
        float e = expf(p[j]*kScaling - mx);
        p[j] = e; sum += e;
    }
    red[tid] = sum; __syncthreads();
    for (int o = 128; o > 0; o >>= 1) { if (tid < o) red[tid] += red[tid+o]; __syncthreads(); }
    float inv = 1.f / red[0];
    for (int j = tid; j < n; j += 256) p[j] *= inv;
    for (int j = n + tid; j < zend; j += 256) p[j] = 0.f;
}

__global__ void __launch_bounds__(256) router_kernel(
    const float* __restrict__ t, const float* __restrict__ rw)
{
    int row = blockIdx.x, tid = threadIdx.x;
    float acc[NEXP] = {};
    const float* xr = t + (ll)row*DIM;
    for (int d = tid; d < DIM; d += 256) {
        float x = xr[d];
        const float* r = rw + d*NEXP;
#pragma unroll
        for (int e = 0; e < NEXP; e++) acc[e] = fmaf(x, r[e], acc[e]);
    }
    __shared__ float red[NEXP][256];
#pragma unroll
    for (int e = 0; e < NEXP; e++) red[e][tid] = acc[e];
    __syncthreads();
    for (int o = 128; o > 0; o >>= 1) {
        if (tid < o)
#pragma unroll
            for (int e = 0; e < NEXP; e++) red[e][tid] += red[e][tid+o];
        __syncthreads();
    }
    if (tid == 0) {
        float best = red[0][0]; int bi = 0;
#pragma unroll
        for (int e = 1; e < NEXP; e++) if (red[e][0] > best) { best = red[e][0]; bi = e; }
        g_eidx[row] = bi;
        g_gateval[row] = 1.f / (1.f + expf(-best));
        atomicAdd(&g_hist[bi], 1);
    }
}

__global__ void zero8_kernel() {
    int i = threadIdx.x;
    if (i < NEXP) { g_hist[i] = 0; g_ctr[i] = 0; }
}

__global__ void prefix_kernel() {
    if (threadIdx.x == 0) {
        int s = 0;
        for (int e = 0; e < NEXP; e++) { g_seg_start[e] = s; g_seg_count[e] = g_hist[e]; s += g_hist[e]; }
        g_seg_start[NEXP] = s;
    }
}

__global__ void scatter_kernel() {
    int tk = blockIdx.x*256 + threadIdx.x;
    if (tk < NTOK) {
        int e = g_eidx[tk];
        int pos = atomicAdd(&g_ctr[e], 1);
        g_perm[g_seg_start[e] + pos] = tk;
    }
}

__global__ void __launch_bounds__(256) gather_scale_kernel(const float* __restrict__ t) {
    int i = blockIdx.x;
    int s = g_perm[i];
    float g = g_gateval[s];
    const float* src = t + (ll)s*DIM;
    float* dst = g_tg + (ll)i*DIM;
    for (int d = threadIdx.x; d < DIM; d += 256) dst[d] = src[d]*g;
}

__global__ void __launch_bounds__(256) act_routed_kernel(
    const float* __restrict__ gu, float* __restrict__ act)
{
    ll i = (ll)blockIdx.x*256 + threadIdx.x;
    ll row = i >> 11, f = i & (FDIM-1);
    float g = gu[row*2*FDIM + f];
    float u = gu[row*2*FDIM + FDIM + f];
    act[i] = u * (g / (1.f + expf(-g)));
}

__global__ void __launch_bounds__(256) swiglu_kernel(
    float* __restrict__ g, const float* __restrict__ u)
{
    ll i = (ll)blockIdx.x*256 + threadIdx.x;
    float x = g[i];
    g[i] = u[i] * (x / (1.f + expf(-x)));
}

__global__ void __launch_bounds__(256) final_add_kernel(
    const float* __restrict__ hs2, const float* __restrict__ shared_,
    const float* __restrict__ routed, float* __restrict__ out)
{
    ll i = (ll)blockIdx.x*256 + threadIdx.x;
    out[i] = hs2[i] + shared_[i] + routed[i];
}

// ----------------------------- launcher ------------------------------------
static float* symf(const void* sym) { void* p = nullptr; cudaGetSymbolAddress(&p, sym); return (float*)p; }

extern "C" void kernel_launch(void* const* d_in, const int* in_sizes, int n_in,
                              void* d_out, int out_size)
{
    (void)in_sizes; (void)n_in; (void)out_size;
    const float* hidden = (const float*)d_in[0];
    const float* fcos   = (const float*)d_in[1];
    const float* fsin   = (const float*)d_in[2];
    const float* wq     = (const float*)d_in[5];
    const float* wk     = (const float*)d_in[6];
    const float* wv     = (const float*)d_in[7];
    const float* wo     = (const float*)d_in[8];
    const float* ln1    = (const float*)d_in[9];
    const float* ln2    = (const float*)d_in[10];
    const float* rw     = (const float*)d_in[11];
    const float* gup    = (const float*)d_in[12];
    const float* dwn    = (const float*)d_in[13];
    const float* sgw    = (const float*)d_in[14];
    const float* suw    = (const float*)d_in[15];
    const float* sdw    = (const float*)d_in[16];
    float* out = (float*)d_out;

    float* hsn    = symf(g_hsn);
    float* qb     = symf(g_q);
    float* kb     = symf(g_k);
    float* vb     = symf(g_v);
    float* sc     = symf(g_scores);
    float* attn   = symf(g_attn);
    float* hs2    = symf(g_hs2);
    float* tb     = symf(g_t);
    float* tg     = symf(g_tg);
    float* gu     = symf(g_gu);
    float* actb   = symf(g_act);
    float* routed = symf(g_routed);
    float* sg     = symf(g_sg);
    float* su     = symf(g_su);
    float* shd    = symf(g_shared);

    cudaFuncSetAttribute(hm_dense,  cudaFuncAttributeMaxDynamicSharedMemorySize, SMEM_BYTES);
    cudaFuncSetAttribute(hm_dense2, cudaFuncAttributeMaxDynamicSharedMemorySize, SMEM_BYTES);
    cudaFuncSetAttribute(hm_qk,     cudaFuncAttributeMaxDynamicSharedMemorySize, SMEM_BYTES);
    cudaFuncSetAttribute(hm_pv,     cudaFuncAttributeMaxDynamicSharedMemorySize, SMEM_BYTES);
    cudaFuncSetAttribute(hm_gateup, cudaFuncAttributeMaxDynamicSharedMemorySize, SMEM_BYTES);
    cudaFuncSetAttribute(hm_down,   cudaFuncAttributeMaxDynamicSharedMemorySize, SMEM_BYTES);

    // 1) pre-attn RMSNorm
    rmsnorm_kernel<<<NTOK, 256>>>(hidden, ln1, hsn);
    // 2) QKV projections
    hm_dense <<<dim3(16,32),   256, SMEM_BYTES>>>(hsn, wq, qb, nullptr, NTOK, DIM, DIM, DIM, DIM);
    hm_dense2<<<dim3(16,8,2),  256, SMEM_BYTES>>>(hsn, wk, kb, wv, vb, NTOK, DIM, DIM, KVD, KVD);
    // 3) RoPE + L2 norm
    rope_l2_kernel<<<dim3(SQ, NHEADS), 64>>>(qb, fcos, fsin, DIM);
    rope_l2_kernel<<<dim3(SQ, NKV),    64>>>(kb, fcos, fsin, KVD);
    // 4) scores = Q K^T (causal tile skip)
    hm_qk<<<dim3(16,32,NHEADS), 256, SMEM_BYTES>>>(qb, kb, sc);
    // 5) causal softmax
    softmax_causal<<<dim3(SQ, NHEADS), 256>>>(sc);
    // 6) attn = P V (K capped causally)
    hm_pv<<<dim3(16,2,NHEADS), 256, SMEM_BYTES>>>(sc, vb, attn);
    // 7) output proj + residual
    hm_dense<<<dim3(16,32), 256, SMEM_BYTES>>>(attn, wo, hs2, hidden, NTOK, DIM, DIM, DIM, DIM);
    // 8) post-attn RMSNorm
    rmsnorm_kernel<<<NTOK, 256>>>(hs2, ln2, tb);
    // 9) router
    zero8_kernel<<<1, 32>>>();
    router_kernel<<<NTOK, 256>>>(tb, rw);
    prefix_kernel<<<1, 32>>>();
    scatter_kernel<<<8, 256>>>();
    gather_scale_kernel<<<NTOK, 256>>>(tb);
    // 10) routed expert
    hm_gateup<<<dim3(16,64,NEXP), 256, SMEM_BYTES>>>(tg, gup, gu);
    act_routed_kernel<<<(NTOK*FDIM)/256, 256>>>(gu, actb);
    hm_down<<<dim3(16,32,NEXP), 256, SMEM_BYTES>>>(actb, dwn, routed);
    // 11) shared expert
    hm_dense2<<<dim3(16,32,2), 256, SMEM_BYTES>>>(tb, sgw, sg, suw, su, NTOK, DIM, DIM, FDIM, FDIM);
    swiglu_kernel<<<(NTOK*FDIM)/256, 256>>>(sg, su);
    hm_dense<<<dim3(16,32), 256, SMEM_BYTES>>>(sg, sdw, shd, nullptr, NTOK, FDIM, FDIM, DIM, DIM);
    // 12) final residual + shared + routed
    final_add_kernel<<<(NTOK*DIM)/256, 256>>>(hs2, shd, routed, out);
}

// round 7
// speedup vs baseline: 2.1568x; 1.8656x over previous
#include <cuda_runtime.h>
#include <cuda_bf16.h>
#include <cstdint>
#include <math.h>

typedef long long ll;

#define SQ     2048
#define DIM    2048
#define NHEADS 16
#define NKV    4
#define HDIM   128
#define KVD    512
#define NEXP   8
#define FDIM   2048
#define NTOK   2048

#define BM 128
#define BN 64
#define BK 32
#define LDA2 20   // A row stride in uint2 slots (16 k-pairs + 4 pad); 20%16==4 -> conflict-free
#define LDB2 68   // B j-row stride in uint2 slots (64 n + 4 pad); 68%16==4 -> conflict-free
#define SMEM_A_BYTES (BM*LDA2*8)            // 20480
#define SMEM_B_BYTES ((BK/2)*LDB2*8)        // 8704
#define SMEM_BYTES   (SMEM_A_BYTES + SMEM_B_BYTES)   // 29184

static const float kScaling = 0.08838834764831845f;  // 128^-0.5

// ----------------------------- scratch (device globals) --------------------
__device__ float g_hsn   [(ll)NTOK*DIM];
__device__ float g_q     [(ll)NTOK*DIM];
__device__ float g_k     [(ll)NTOK*KVD];
__device__ float g_v     [(ll)NTOK*KVD];
__device__ float g_scores[(ll)NHEADS*SQ*SQ];   // 256 MB
__device__ float g_attn  [(ll)NTOK*DIM];
__device__ float g_hs2   [(ll)NTOK*DIM];
__device__ float g_t     [(ll)NTOK*DIM];
__device__ float g_tg    [(ll)NTOK*DIM];
__device__ float g_gu    [(ll)NTOK*2*FDIM];
__device__ float g_act   [(ll)NTOK*FDIM];
__device__ float g_routed[(ll)NTOK*DIM];
__device__ float g_sg    [(ll)NTOK*FDIM];
__device__ float g_su    [(ll)NTOK*FDIM];
__device__ float g_shared[(ll)NTOK*DIM];
__device__ int   g_eidx[NTOK];
__device__ float g_gateval[NTOK];
__device__ int   g_hist[NEXP], g_ctr[NEXP], g_seg_start[NEXP+1], g_seg_count[NEXP];
__device__ int   g_perm[NTOK];

// ----------------------------- helpers -------------------------------------
// Split two fp32 values into fp16 hi/lo pairs: returns {pack(hx,hy), pack(lx,ly)}.
// Opaque asm so no compiler transform can fold the residual computation.
__device__ __forceinline__ uint2 hsplit2(float x, float y) {
    uint2 r;
    asm("{\n\t"
        ".reg .b16 h0,h1,l0,l1;\n\t"
        ".reg .f32 fx,fy;\n\t"
        "cvt.rn.f16.f32 h0, %2;\n\t"
        "cvt.f32.f16 fx, h0;\n\t"
        "sub.f32 fx, %2, fx;\n\t"
        "cvt.rn.f16.f32 l0, fx;\n\t"
        "cvt.rn.f16.f32 h1, %3;\n\t"
        "cvt.f32.f16 fy, h1;\n\t"
        "sub.f32 fy, %3, fy;\n\t"
        "cvt.rn.f16.f32 l1, fy;\n\t"
        "mov.b32 %0, {h0,h1};\n\t"
        "mov.b32 %1, {l0,l1};\n\t"
        "}" : "=r"(r.x), "=r"(r.y) : "f"(x), "f"(y));
    return r;
}
__device__ __forceinline__ void mma_f16(float* c, uint32_t a0, uint32_t a1, uint32_t a2, uint32_t a3,
                                        uint32_t b0, uint32_t b1) {
    asm volatile("mma.sync.aligned.m16n8k16.row.col.f32.f16.f16.f32 "
        "{%0,%1,%2,%3}, {%4,%5,%6,%7}, {%8,%9}, {%0,%1,%2,%3};"
        : "+f"(c[0]), "+f"(c[1]), "+f"(c[2]), "+f"(c[3])
        : "r"(a0), "r"(a1), "r"(a2), "r"(a3), "r"(b0), "r"(b1));
}

// ----------------------------- tensor GEMM body ----------------------------
// C[M,N] = A[M,K] * B, fp32 via 3-term fp16 split (Ah*Bh + Ah*Bl + Al*Bh).
// SMEM: As[m][j] uint2{hi2,lo2} for k-pair j=k/2; Bs[j][n] uint2{hi2,lo2} (pairs along k).
// BMODE=0: B is [N,K] row-major. BMODE=1: B is [K,N] row-major.
// KCAP: limit K to m0+BM (causal PV). RM: scatter C rows through rowmap.
template<int BMODE, bool KCAP, bool RM>
__device__ __forceinline__ void hm_body(
    const float* __restrict__ A, const float* __restrict__ B,
    float* __restrict__ C, const float* __restrict__ Cadd,
    int M, int K, int lda, int ldb, int ldc, int m0, int n0,
    const int* __restrict__ rowmap)
{
    extern __shared__ char smem[];
    uint2* As = reinterpret_cast<uint2*>(smem);
    uint2* Bs = reinterpret_cast<uint2*>(smem + SMEM_A_BYTES);

    const int tid = threadIdx.x;
    const int wid = tid >> 5, lid = tid & 31;
    const int wm = (wid & 3) << 5;       // warp M offset: 0,32,64,96
    const int wn = (wid >> 2) << 5;      // warp N offset: 0,32
    const int lr = lid >> 2;             // groupID: 0..7
    const int ca = lid & 3;              // thread-in-group: 0..3
    const int lc = ca << 1;

    float acc[2][4][4];
#pragma unroll
    for (int i = 0; i < 2; i++)
#pragma unroll
        for (int j = 0; j < 4; j++)
#pragma unroll
            for (int q = 0; q < 4; q++) acc[i][j][q] = 0.f;

    int Keff = K;
    if (KCAP) Keff = min(K, m0 + BM);
    const int nch = Keff >> 5;   // BK=32 chunks

    const int b_kr2 = tid >> 4;            // BMODE=1: k-pair index 0..15
    const int b_n4  = (tid & 15) << 2;     // BMODE=1: n offset

    float4 va[4], vb[2];

    // ---- prologue: load chunk 0 into regs ----
    {
        const int k0 = 0;
#pragma unroll
        for (int i = 0; i < 4; i++) {
            int idx = tid + (i << 8);
            int row = idx >> 3, c4 = (idx & 7) << 2;
            va[i] = make_float4(0.f, 0.f, 0.f, 0.f);
            if ((m0 + row) < M)
                va[i] = *reinterpret_cast<const float4*>(A + (ll)(m0 + row)*lda + k0 + c4);
        }
        if (BMODE == 1) {
            vb[0] = *reinterpret_cast<const float4*>(B + (ll)(k0 + 2*b_kr2    )*ldb + n0 + b_n4);
            vb[1] = *reinterpret_cast<const float4*>(B + (ll)(k0 + 2*b_kr2 + 1)*ldb + n0 + b_n4);
        } else {
#pragma unroll
            for (int i = 0; i < 2; i++) {
                int idx = tid + (i << 8);
                int n = idx & 63, kc4 = (idx >> 6) << 2;
                vb[i] = *reinterpret_cast<const float4*>(B + (ll)(n0 + n)*ldb + k0 + kc4);
            }
        }
    }

    for (int c = 0; c < nch; c++) {
        // ---- store current chunk regs -> smem (fp16 hi/lo split once) ----
#pragma unroll
        for (int i = 0; i < 4; i++) {
            int idx = tid + (i << 8);
            int row = idx >> 3, c4 = (idx & 7) << 2;
            int j0 = c4 >> 1;
            As[row*LDA2 + j0    ] = hsplit2(va[i].x, va[i].y);
            As[row*LDA2 + j0 + 1] = hsplit2(va[i].z, va[i].w);
        }
        if (BMODE == 1) {
            Bs[b_kr2*LDB2 + b_n4 + 0] = hsplit2(vb[0].x, vb[1].x);
            Bs[b_kr2*LDB2 + b_n4 + 1] = hsplit2(vb[0].y, vb[1].y);
            Bs[b_kr2*LDB2 + b_n4 + 2] = hsplit2(vb[0].z, vb[1].z);
            Bs[b_kr2*LDB2 + b_n4 + 3] = hsplit2(vb[0].w, vb[1].w);
        } else {
#pragma unroll
            for (int i = 0; i < 2; i++) {
                int idx = tid + (i << 8);
                int n = idx & 63, kc4 = (idx >> 6) << 2;
                int j0 = kc4 >> 1;
                Bs[ j0     *LDB2 + n] = hsplit2(vb[i].x, vb[i].y);
                Bs[(j0 + 1)*LDB2 + n] = hsplit2(vb[i].z, vb[i].w);
            }
        }
        __syncthreads();

        // ---- prefetch next chunk into regs ----
        if (c + 1 < nch) {
            const int k0 = (c + 1) << 5;
#pragma unroll
            for (int i = 0; i < 4; i++) {
                int idx = tid + (i << 8);
                int row = idx >> 3, c4 = (idx & 7) << 2;
                va[i] = make_float4(0.f, 0.f, 0.f, 0.f);
                if ((m0 + row) < M)
                    va[i] = *reinterpret_cast<const float4*>(A + (ll)(m0 + row)*lda + k0 + c4);
            }
            if (BMODE == 1) {
                vb[0] = *reinterpret_cast<const float4*>(B + (ll)(k0 + 2*b_kr2    )*ldb + n0 + b_n4);
                vb[1] = *reinterpret_cast<const float4*>(B + (ll)(k0 + 2*b_kr2 + 1)*ldb + n0 + b_n4);
            } else {
#pragma unroll
                for (int i = 0; i < 2; i++) {
                    int idx = tid + (i << 8);
                    int n = idx & 63, kc4 = (idx >> 6) << 2;
                    vb[i] = *reinterpret_cast<const float4*>(B + (ll)(n0 + n)*ldb + k0 + kc4);
                }
            }
        }

        // ---- compute: 2 k16-steps ----
#pragma unroll
        for (int s = 0; s < 2; s++) {
            const int jb = s << 3;
            uint2 bfr[4][2];
#pragma unroll
            for (int nt = 0; nt < 4; nt++) {
                int n = wn + nt*8 + lr;
                bfr[nt][0] = Bs[(jb + ca    )*LDB2 + n];
                bfr[nt][1] = Bs[(jb + ca + 4)*LDB2 + n];
            }
#pragma unroll
            for (int mt = 0; mt < 2; mt++) {
                int r = wm + mt*16 + lr;
                uint2 a0 = As[ r     *LDA2 + jb + ca    ];
                uint2 a1 = As[(r + 8)*LDA2 + jb + ca    ];
                uint2 a2 = As[ r     *LDA2 + jb + ca + 4];
                uint2 a3 = As[(r + 8)*LDA2 + jb + ca + 4];
#pragma unroll
                for (int nt = 0; nt < 4; nt++) {
                    mma_f16(acc[mt][nt], a0.x, a1.x, a2.x, a3.x, bfr[nt][0].x, bfr[nt][1].x);
                    mma_f16(acc[mt][nt], a0.x, a1.x, a2.x, a3.x, bfr[nt][0].y, bfr[nt][1].y);
                    mma_f16(acc[mt][nt], a0.y, a1.y, a2.y, a3.y, bfr[nt][0].x, bfr[nt][1].x);
                }
            }
        }
        __syncthreads();
    }

    // ---- epilogue ----
#pragma unroll
    for (int mt = 0; mt < 2; mt++) {
        int mbase = m0 + wm + mt*16 + lr;
#pragma unroll
        for (int half = 0; half < 2; half++) {
            int m = mbase + half*8;
            if (m < M) {
                int srow = RM ? rowmap[m] : m;
#pragma unroll
                for (int nt = 0; nt < 4; nt++) {
                    int n = n0 + wn + nt*8 + lc;
                    float2 v = half ? make_float2(acc[mt][nt][2], acc[mt][nt][3])
                                    : make_float2(acc[mt][nt][0], acc[mt][nt][1]);
                    if (Cadd) {
                        float2 a = *reinterpret_cast<const float2*>(Cadd + (ll)m*ldc + n);
                        v.x += a.x; v.y += a.y;
                    }
                    *reinterpret_cast<float2*>(C + (ll)srow*ldc + n) = v;
                }
            }
        }
    }
}

// ----------------------------- GEMM wrappers -------------------------------
__global__ void __launch_bounds__(256, 2) hm_dense(
    const float* __restrict__ A, const float* __restrict__ B,
    float* __restrict__ C, const float* __restrict__ Cadd,
    int M, int K, int lda, int ldb, int ldc)
{
    hm_body<1, false, false>(A, B, C, Cadd, M, K, lda, ldb, ldc,
                             blockIdx.x << 7, blockIdx.y << 6, nullptr);
}

__global__ void __launch_bounds__(256, 2) hm_dense2(
    const float* __restrict__ A,
    const float* __restrict__ B0, float* __restrict__ C0,
    const float* __restrict__ B1, float* __restrict__ C1,
    int M, int K, int lda, int ldb, int ldc)
{
    const float* B = blockIdx.z ? B1 : B0;
    float* C = blockIdx.z ? C1 : C0;
    hm_body<1, false, false>(A, B, C, nullptr, M, K, lda, ldb, ldc,
                             blockIdx.x << 7, blockIdx.y << 6, nullptr);
}

__global__ void __launch_bounds__(256, 2) hm_qk(
    const float* __restrict__ q, const float* __restrict__ k, float* __restrict__ scv)
{
    int h = blockIdx.z;
    int m0 = blockIdx.x << 7, n0 = blockIdx.y << 6;
    if (n0 > m0 + (BM - 1)) return;   // fully-masked causal tile
    hm_body<0, false, false>(q + h*HDIM, k + (h >> 2)*HDIM, scv + (ll)h*SQ*SQ, nullptr,
                             SQ, HDIM, DIM, KVD, SQ, m0, n0, nullptr);
}

__global__ void __launch_bounds__(256, 2) hm_pv(
    const float* __restrict__ p, const float* __restrict__ v, float* __restrict__ attn)
{
    int h = blockIdx.z;
    hm_body<1, true, false>(p + (ll)h*SQ*SQ, v + (h >> 2)*HDIM, attn + h*HDIM, nullptr,
                            SQ, SQ, SQ, KVD, DIM, blockIdx.x << 7, blockIdx.y << 6, nullptr);
}

__global__ void __launch_bounds__(256, 2) hm_gateup(
    const float* __restrict__ tg, const float* __restrict__ gup, float* __restrict__ gu)
{
    int e = blockIdx.z;
    int cnt = g_seg_count[e];
    int m0 = blockIdx.x << 7;
    if (m0 >= cnt) return;
    int st = g_seg_start[e];
    hm_body<1, false, false>(tg + (ll)st*DIM, gup + (ll)e*DIM*2*FDIM, gu + (ll)st*2*FDIM, nullptr,
                             cnt, DIM, DIM, 2*FDIM, 2*FDIM, m0, blockIdx.y << 6, nullptr);
}

__global__ void __launch_bounds__(256, 2) hm_down(
    const float* __restrict__ act, const float* __restrict__ dwn, float* __restrict__ outr)
{
    int e = blockIdx.z;
    int cnt = g_seg_count[e];
    int m0 = blockIdx.x << 7;
    if (m0 >= cnt) return;
    int st = g_seg_start[e];
    hm_body<1, false, true>(act + (ll)st*FDIM, dwn + (ll)e*FDIM*DIM, outr, nullptr,
                            cnt, FDIM, FDIM, DIM, DIM, m0, blockIdx.y << 6, g_perm + st);
}

// ----------------------------- elementwise / norm kernels ------------------
__global__ void __launch_bounds__(256) rmsnorm_kernel(
    const float* __restrict__ x, const float* __restrict__ w, float* __restrict__ y)
{
    int row = blockIdx.x, tid = threadIdx.x;
    const float* xr = x + (ll)row*DIM;
    float s = 0.f;
    for (int d = tid; d < DIM; d += 256) { float v = xr[d]; s = fmaf(v, v, s); }
    __shared__ float red[256];
    red[tid] = s; __syncthreads();
    for (int o = 128; o > 0; o >>= 1) { if (tid < o) red[tid] += red[tid+o]; __syncthreads(); }
    float inv = rsqrtf(red[0] * (1.0f/DIM) + 1e-5f);
    float* yr = y + (ll)row*DIM;
    for (int d = tid; d < DIM; d += 256) yr[d] = xr[d] * inv * w[d];
}

__global__ void rope_l2_kernel(float* __restrict__ buf, const float* __restrict__ cosb,
                               const float* __restrict__ sinb, int ld)
{
    int s = blockIdx.x, h = blockIdx.y, j = threadIdx.x;  // j: 0..63
    float* p = buf + (ll)s*ld + h*HDIM;
    float a = p[2*j], b = p[2*j+1];
    float c  = cosb[s*64 + j];
    float sn = sinb[s*64 + j];
    float na = a*c - b*sn;
    float nb = a*sn + b*c;
    __shared__ float red[64];
    red[j] = na*na + nb*nb; __syncthreads();
    for (int o = 32; o > 0; o >>= 1) { if (j < o) red[j] += red[j+o]; __syncthreads(); }
    float scale = rsqrtf(red[0] * (1.0f/HDIM) + 1e-6f);
    p[2*j]   = na * scale;
    p[2*j+1] = nb * scale;
}

__global__ void __launch_bounds__(256) softmax_causal(float* __restrict__ scores)
{
    int row = blockIdx.x, h = blockIdx.y, tid = threadIdx.x;
    float* p = scores + ((ll)h*SQ + row)*SQ;
    int n = row + 1;
    int zend = ((row >> 7) << 7) + 128;   // PV only reads k < m0+128
    __shared__ float red[256];
    float mx = -1e30f;
    for (int j = tid; j < n; j += 256) mx = fmaxf(mx, p[j]*kScaling);
    red[tid] = mx; __syncthreads();
    for (int o = 128; o > 0; o >>= 1) { if (tid < o) red[tid] = fmaxf(red[tid], red[tid+o]); __syncthreads(); }
    mx = red[0]; __syncthreads();
    float sum = 0.f;
    for (int j = tid; j < n; j += 256) {
        float e = expf(p[j]*kScaling - mx);
        p[j] = e; sum += e;
    }
    red[tid] = sum; __syncthreads();
    for (int o = 128; o > 0; o >>= 1) { if (tid < o) red[tid] += red[tid+o]; __syncthreads(); }
    float inv = 1.f / red[0];
    for (int j = tid; j < n; j += 256) p[j] *= inv;
    for (int j = n + tid; j < zend; j += 256) p[j] = 0.f;
}

__global__ void __launch_bounds__(256) router_kernel(
    const float* __restrict__ t, const float* __restrict__ rw)
{
    int row = blockIdx.x, tid = threadIdx.x;
    float acc[NEXP] = {};
    const float* xr = t + (ll)row*DIM;
    for (int d = tid; d < DIM; d += 256) {
        float x = xr[d];
        const float* r = rw + d*NEXP;
#pragma unroll
        for (int e = 0; e < NEXP; e++) acc[e] = fmaf(x, r[e], acc[e]);
    }
    __shared__ float red[NEXP][256];
#pragma unroll
    for (int e = 0; e < NEXP; e++) red[e][tid] = acc[e];
    __syncthreads();
    for (int o = 128; o > 0; o >>= 1) {
        if (tid < o)
#pragma unroll
            for (int e = 0; e < NEXP; e++) red[e][tid] += red[e][tid+o];
        __syncthreads();
    }
    if (tid == 0) {
        float best = red[0][0]; int bi = 0;
#pragma unroll
        for (int e = 1; e < NEXP; e++) if (red[e][0] > best) { best = red[e][0]; bi = e; }
        g_eidx[row] = bi;
        g_gateval[row] = 1.f / (1.f + expf(-best));
        atomicAdd(&g_hist[bi], 1);
    }
}

__global__ void zero8_kernel() {
    int i = threadIdx.x;
    if (i < NEXP) { g_hist[i] = 0; g_ctr[i] = 0; }
}

__global__ void prefix_kernel() {
    if (threadIdx.x == 0) {
        int s = 0;
        for (int e = 0; e < NEXP; e++) { g_seg_start[e] = s; g_seg_count[e] = g_hist[e]; s += g_hist[e]; }
        g_seg_start[NEXP] = s;
    }
}

__global__ void scatter_kernel() {
    int tk = blockIdx.x*256 + threadIdx.x;
    if (tk < NTOK) {
        int e = g_eidx[tk];
        int pos = atomicAdd(&g_ctr[e], 1);
        g_perm[g_seg_start[e] + pos] = tk;
    }
}

__global__ void __launch_bounds__(256) gather_scale_kernel(const float* __restrict__ t) {
    int i = blockIdx.x;
    int s = g_perm[i];
    float g = g_gateval[s];
    const float* src = t + (ll)s*DIM;
    float* dst = g_tg + (ll)i*DIM;
    for (int d = threadIdx.x; d < DIM; d += 256) dst[d] = src[d]*g;
}

__global__ void __launch_bounds__(256) act_routed_kernel(
    const float* __restrict__ gu, float* __restrict__ act)
{
    ll i = (ll)blockIdx.x*256 + threadIdx.x;
    ll row = i >> 11, f = i & (FDIM-1);
    float g = gu[row*2*FDIM + f];
    float u = gu[row*2*FDIM + FDIM + f];
    act[i] = u * (g / (1.f + expf(-g)));
}

__global__ void __launch_bounds__(256) swiglu_kernel(
    float* __restrict__ g, const float* __restrict__ u)
{
    ll i = (ll)blockIdx.x*256 + threadIdx.x;
    float x = g[i];
    g[i] = u[i] * (x / (1.f + expf(-x)));
}

__global__ void __launch_bounds__(256) final_add_kernel(
    const float* __restrict__ hs2, const float* __restrict__ shared_,
    const float* __restrict__ routed, float* __restrict__ out)
{
    ll i = (ll)blockIdx.x*256 + threadIdx.x;
    out[i] = hs2[i] + shared_[i] + routed[i];
}

// ----------------------------- launcher ------------------------------------
static float* symf(const void* sym) { void* p = nullptr; cudaGetSymbolAddress(&p, sym); return (float*)p; }

extern "C" void kernel_launch(void* const* d_in, const int* in_sizes, int n_in,
                              void* d_out, int out_size)
{
    (void)in_sizes; (void)n_in; (void)out_size;
    const float* hidden = (const float*)d_in[0];
    const float* fcos   = (const float*)d_in[1];
    const float* fsin   = (const float*)d_in[2];
    const float* wq     = (const float*)d_in[5];
    const float* wk     = (const float*)d_in[6];
    const float* wv     = (const float*)d_in[7];
    const float* wo     = (const float*)d_in[8];
    const float* ln1    = (const float*)d_in[9];
    const float* ln2    = (const float*)d_in[10];
    const float* rw     = (const float*)d_in[11];
    const float* gup    = (const float*)d_in[12];
    const float* dwn    = (const float*)d_in[13];
    const float* sgw    = (const float*)d_in[14];
    const float* suw    = (const float*)d_in[15];
    const float* sdw    = (const float*)d_in[16];
    float* out = (float*)d_out;

    float* hsn    = symf(g_hsn);
    float* qb     = symf(g_q);
    float* kb     = symf(g_k);
    float* vb     = symf(g_v);
    float* sc     = symf(g_scores);
    float* attn   = symf(g_attn);
    float* hs2    = symf(g_hs2);
    float* tb     = symf(g_t);
    float* tg     = symf(g_tg);
    float* gu     = symf(g_gu);
    float* actb   = symf(g_act);
    float* routed = symf(g_routed);
    float* sg     = symf(g_sg);
    float* su     = symf(g_su);
    float* shd    = symf(g_shared);

    cudaFuncSetAttribute(hm_dense,  cudaFuncAttributeMaxDynamicSharedMemorySize, SMEM_BYTES);
    cudaFuncSetAttribute(hm_dense2, cudaFuncAttributeMaxDynamicSharedMemorySize, SMEM_BYTES);
    cudaFuncSetAttribute(hm_qk,     cudaFuncAttributeMaxDynamicSharedMemorySize, SMEM_BYTES);
    cudaFuncSetAttribute(hm_pv,     cudaFuncAttributeMaxDynamicSharedMemorySize, SMEM_BYTES);
    cudaFuncSetAttribute(hm_gateup, cudaFuncAttributeMaxDynamicSharedMemorySize, SMEM_BYTES);
    cudaFuncSetAttribute(hm_down,   cudaFuncAttributeMaxDynamicSharedMemorySize, SMEM_BYTES);

    // 1) pre-attn RMSNorm
    rmsnorm_kernel<<<NTOK, 256>>>(hidden, ln1, hsn);
    // 2) QKV projections
    hm_dense <<<dim3(16,32),   256, SMEM_BYTES>>>(hsn, wq, qb, nullptr, NTOK, DIM, DIM, DIM, DIM);
    hm_dense2<<<dim3(16,8,2),  256, SMEM_BYTES>>>(hsn, wk, kb, wv, vb, NTOK, DIM, DIM, KVD, KVD);
    // 3) RoPE + L2 norm
    rope_l2_kernel<<<dim3(SQ, NHEADS), 64>>>(qb, fcos, fsin, DIM);
    rope_l2_kernel<<<dim3(SQ, NKV),    64>>>(kb, fcos, fsin, KVD);
    // 4) scores = Q K^T (causal tile skip)
    hm_qk<<<dim3(16,32,NHEADS), 256, SMEM_BYTES>>>(qb, kb, sc);
    // 5) causal softmax
    softmax_causal<<<dim3(SQ, NHEADS), 256>>>(sc);
    // 6) attn = P V (K capped causally)
    hm_pv<<<dim3(16,2,NHEADS), 256, SMEM_BYTES>>>(sc, vb, attn);
    // 7) output proj + residual
    hm_dense<<<dim3(16,32), 256, SMEM_BYTES>>>(attn, wo, hs2, hidden, NTOK, DIM, DIM, DIM, DIM);
    // 8) post-attn RMSNorm
    rmsnorm_kernel<<<NTOK, 256>>>(hs2, ln2, tb);
    // 9) router
    zero8_kernel<<<1, 32>>>();
    router_kernel<<<NTOK, 256>>>(tb, rw);
    prefix_kernel<<<1, 32>>>();
    scatter_kernel<<<8, 256>>>();
    gather_scale_kernel<<<NTOK, 256>>>(tb);
    // 10) routed expert
    hm_gateup<<<dim3(16,64,NEXP), 256, SMEM_BYTES>>>(tg, gup, gu);
    act_routed_kernel<<<(NTOK*FDIM)/256, 256>>>(gu, actb);
    hm_down<<<dim3(16,32,NEXP), 256, SMEM_BYTES>>>(actb, dwn, routed);
    // 11) shared expert
    hm_dense2<<<dim3(16,32,2), 256, SMEM_BYTES>>>(tb, sgw, sg, suw, su, NTOK, DIM, DIM, FDIM, FDIM);
    swiglu_kernel<<<(NTOK*FDIM)/256, 256>>>(sg, su);
    hm_dense<<<dim3(16,32), 256, SMEM_BYTES>>>(sg, sdw, shd, nullptr, NTOK, FDIM, FDIM, DIM, DIM);
    // 12) final residual + shared + routed
    final_add_kernel<<<(NTOK*DIM)/256, 256>>>(hs2, shd, routed, out);
}